// round 17
// baseline (speedup 1.0000x reference)
#include <cuda_runtime.h>
#include <cuda_fp16.h>
#include <cstdint>

// Problem constants (fixed by the dataset)
#define HH   1024
#define WW   2048
#define GW2  2052            // padded row stride in cells (even, float4-aligned pairs)
#define GH   (HH + 2)        // padded grid height = 1026
#define NCELL (GH * GW2)     // 2,105,352 cells (float2: ~16.8 MB, L2-resident)
#define NPIX (HH * WW)       // 2,097,152
#define COUT 64
#define BN_EPS 1e-5f
#define STATS_BLOCKS 592
#define OUT_BLOCKS 592
#define NWARP 8              // warps per k_output block

// Scratch (static __device__ arrays — zero-initialized at module load).
// Each cell: .x = feature (0 if empty), .y = int bits of (output row + 1); 0 = empty.
__device__ float2 g_cell[NCELL];             // interleaved (feat, idx) grid
__device__ float  g_part[STATS_BLOCKS * 54]; // per-block stat partials
__device__ float  g_wf[9 * COUT];            // BN-folded weights
__device__ float  g_bf[COUT];                // BN-folded bias
__device__ int    g_ctr;                     // last-block counter (reset by last block)

__device__ __forceinline__ uint32_t smem_u32(const void* p) {
    uint32_t a;
    asm("{ .reg .u64 t; cvta.to.shared.u64 t, %1; cvt.u32.u64 %0, t; }"
        : "=r"(a) : "l"(p));
    return a;
}

// ---------------------------------------------------------------------------
// K1: scatter — 4 points per thread, ONE 8 B store per point.
// ---------------------------------------------------------------------------
__global__ __launch_bounds__(256) void k_scatter(
        const int2* __restrict__ coords,
        const float* __restrict__ feats, int n) {
    const int t   = blockIdx.x * blockDim.x + threadIdx.x;
    const int str = gridDim.x * blockDim.x;
    const int nq  = n >> 2;

    for (int i = t; i < nq; i += str) {
        const float4 f  = *reinterpret_cast<const float4*>(feats + 4 * i);
        const int4 c01  = *reinterpret_cast<const int4*>(coords + 4 * i);
        const int4 c23  = *reinterpret_cast<const int4*>(coords + 4 * i + 2);
        const int p = 4 * i;
        g_cell[(c01.x + 1) * GW2 + (c01.y + 1)] = make_float2(f.x, __int_as_float(p + 1));
        g_cell[(c01.z + 1) * GW2 + (c01.w + 1)] = make_float2(f.y, __int_as_float(p + 2));
        g_cell[(c23.x + 1) * GW2 + (c23.y + 1)] = make_float2(f.z, __int_as_float(p + 3));
        g_cell[(c23.z + 1) * GW2 + (c23.w + 1)] = make_float2(f.w, __int_as_float(p + 4));
    }
    for (int i = nq * 4 + t; i < n; i += str) {
        const int2 c = coords[i];
        g_cell[(c.x + 1) * GW2 + (c.y + 1)] = make_float2(feats[i], __int_as_float(i + 1));
    }
}

// ---------------------------------------------------------------------------
// K2: DENSE vectorized stats scan (unchanged, proven) + fused BN fold.
// ---------------------------------------------------------------------------
__global__ __launch_bounds__(256) void k_stats(
        const float* __restrict__ weight,
        const float* __restrict__ gamma,
        const float* __restrict__ beta, int n) {
    float acc[54];
#pragma unroll
    for (int i = 0; i < 54; i++) acc[i] = 0.f;

    const int tid    = blockIdx.x * blockDim.x + threadIdx.x;
    const int stride = gridDim.x * blockDim.x;
    const int nquad  = NPIX / 4;

    for (int Q = tid; Q < nquad; Q += stride) {
        const int q = Q * 4;
        const int y = q >> 11;
        const int x = q & (WW - 1);
        const float2* base = g_cell + y * GW2 + x;

        float v[3][6];
        float mb[4];
#pragma unroll
        for (int r = 0; r < 3; r++) {
            const float4 u0 = *reinterpret_cast<const float4*>(base + r * GW2);
            const float4 u1 = *reinterpret_cast<const float4*>(base + r * GW2 + 2);
            const float4 u2 = *reinterpret_cast<const float4*>(base + r * GW2 + 4);
            v[r][0] = u0.x; v[r][1] = u0.z; v[r][2] = u1.x;
            v[r][3] = u1.z; v[r][4] = u2.x; v[r][5] = u2.z;
            if (r == 1) { mb[0] = u0.w; mb[1] = u1.y; mb[2] = u1.w; mb[3] = u2.y; }
        }
#pragma unroll
        for (int i = 0; i < 4; i++) {
            const float m = (__float_as_int(mb[i]) > 0) ? 1.f : 0.f;
            float s[9];
#pragma unroll
            for (int r = 0; r < 3; r++)
#pragma unroll
                for (int c = 0; c < 3; c++)
                    s[r * 3 + c] = v[r][i + c] * m;
#pragma unroll
            for (int k = 0; k < 9; k++) acc[k] += s[k];
            int idx = 9;
#pragma unroll
            for (int j = 0; j < 9; j++)
#pragma unroll
                for (int k = j; k < 9; k++) acc[idx++] += s[j] * s[k];
        }
    }

    __shared__ float red[54 * 8];
    const int w = threadIdx.x >> 5, lane = threadIdx.x & 31;
#pragma unroll
    for (int i = 0; i < 54; i++) {
        float v2 = acc[i];
#pragma unroll
        for (int o = 16; o; o >>= 1) v2 += __shfl_xor_sync(0xffffffffu, v2, o);
        if (lane == 0) red[i * 8 + w] = v2;
    }
    __syncthreads();
    if (threadIdx.x < 54) {
        float v2 = 0.f;
#pragma unroll
        for (int ww = 0; ww < 8; ww++) v2 += red[threadIdx.x * 8 + ww];
        g_part[blockIdx.x * 54 + threadIdx.x] = v2;
    }

    __shared__ bool is_last;
    __threadfence();
    if (threadIdx.x == 0) {
        int prev = atomicAdd(&g_ctr, 1);
        is_last = (prev == gridDim.x - 1);
    }
    __syncthreads();
    if (!is_last) return;
    if (threadIdx.x == 0) g_ctr = 0;

    __shared__ float st[64];
    {
        const int t = threadIdx.x;
        const int g = t >> 2;
        const int j = t & 3;
        float v2 = 0.f;
        if (g < 54)
            for (int b = j; b < STATS_BLOCKS; b += 4)
                v2 += g_part[b * 54 + g];
        v2 += __shfl_xor_sync(0xffffffffu, v2, 1);
        v2 += __shfl_xor_sync(0xffffffffu, v2, 2);
        if (j == 0 && g < 54) st[g] = v2;
    }
    __syncthreads();

    if (threadIdx.x < COUT) {
        const int t = threadIdx.x;
        float wv[9];
#pragma unroll
        for (int k = 0; k < 9; k++) wv[k] = weight[k * COUT + t];
        const float invn = 1.f / (float)n;

        float mean = 0.f;
#pragma unroll
        for (int k = 0; k < 9; k++) mean += st[k] * wv[k];
        mean *= invn;

        float q = 0.f;
        int idx = 9;
#pragma unroll
        for (int jj = 0; jj < 9; jj++)
#pragma unroll
            for (int k = jj; k < 9; k++) {
                float term = st[idx++] * wv[jj] * wv[k];
                q += (jj == k) ? term : 2.f * term;
            }
        float var   = fmaxf(q * invn - mean * mean, 0.f);
        float scale = gamma[t] * rsqrtf(var + BN_EPS);
#pragma unroll
        for (int k = 0; k < 9; k++) g_wf[k * COUT + t] = wv[k] * scale;
        g_bf[t] = beta[t] - mean * scale;
    }
}

// ---------------------------------------------------------------------------
// K4: HMMA output pass v2 — pipelined, A in fp16 (hi only), B in fp16 hi+lo.
//     Warp-autonomous 32-pixel tiles; per tile:
//       stage(prefetched taps -> fp16 rows, 48 B stride: conflict-free &
//       16 B-aligned for ldmatrix) -> syncwarp -> 2x ldmatrix.x4 (both
//       rowgroups; buffer free) -> ISSUE NEXT TILE'S GATHER (latency hides
//       under mma/store stream) -> 2 rg x 8 nblk x 2 mma (Ah*Bh + Ah*Bl)
//       -> predicated streaming STG.64 (sector-perfect 32 B row chunks).
//     mma layouts identical to the R16 kernel that verified at 1.8e-7.
// ---------------------------------------------------------------------------
__device__ __forceinline__ float bval(int k, int n) {
    return (k < 9) ? g_wf[k * COUT + n] : ((k == 9) ? g_bf[n] : 0.f);
}

__global__ __launch_bounds__(256, 4) void k_output(float* __restrict__ out) {
    // per-warp: A tile 32 rows x 48 B = 384 words; oidx 32
    __shared__ uint32_t s_a[NWARP][384];
    __shared__ int      s_ox[NWARP][32];

    const int tid  = threadIdx.x;
    const int lane = tid & 31;
    const int wid  = tid >> 5;
    const int bg   = lane >> 2;     // fragment group id (0..7)
    const int btg  = lane & 3;      // thread-in-group (0..3)

    // --- B fragments: hi + lo residual (lo costs regs + 1 mma, no staging)
    uint32_t bh[8][2], bl[8][2];
#pragma unroll
    for (int nb = 0; nb < 8; nb++) {
        const int nch = nb * 8 + bg;
#pragma unroll
        for (int r = 0; r < 2; r++) {
            const int k0 = btg * 2 + r * 8;
            const float w0 = bval(k0, nch), w1 = bval(k0 + 1, nch);
            const __half h0 = __float2half_rn(w0), h1 = __float2half_rn(w1);
            const __half l0 = __float2half_rn(w0 - __half2float(h0));
            const __half l1 = __float2half_rn(w1 - __half2float(h1));
            __half2 hh = __halves2half2(h0, h1);
            __half2 ll = __halves2half2(l0, l1);
            bh[nb][r] = *reinterpret_cast<uint32_t*>(&hh);
            bl[nb][r] = *reinterpret_cast<uint32_t*>(&ll);
        }
    }

    const uint32_t abase = smem_u32(&s_a[wid][0]);
    float2* out2 = reinterpret_cast<float2*>(out);

    const int gw = (blockIdx.x * 256 + tid) >> 5;
    const int nwarps = (gridDim.x * 256) >> 5;    // 4736
    const int ntiles = NPIX / 32;                 // 65536

    // --- prologue: gather tile gw's taps
    float s[9];
    int   oidx;
    {
        const int q0 = gw * 32;
        const float2* rb = g_cell + (q0 >> 11) * GW2 + (q0 & (WW - 1)) + lane;
        const float2 center = rb[GW2 + 1];
        oidx = __float_as_int(center.y);
        s[0] = rb[0].x;       s[1] = rb[1].x;       s[2] = rb[2].x;
        s[3] = rb[GW2].x;     s[4] = center.x;      s[5] = rb[GW2 + 2].x;
        s[6] = rb[2*GW2].x;   s[7] = rb[2*GW2+1].x; s[8] = rb[2*GW2+2].x;
    }

    for (int tile = gw; tile < ntiles; tile += nwarps) {
        // --- stage current tile (lane = its own pixel), fp16 hi only
        s_ox[wid][lane] = oidx;
        {
            __half2 h0 = __floats2half2_rn(s[0], s[1]);
            __half2 h1 = __floats2half2_rn(s[2], s[3]);
            __half2 h2 = __floats2half2_rn(s[4], s[5]);
            __half2 h3 = __floats2half2_rn(s[6], s[7]);
            __half2 h4 = __floats2half2_rn(s[8], 1.0f);   // tap9 = 1 -> bias row
            uint4* rh = reinterpret_cast<uint4*>(&s_a[wid][lane * 12]);
            rh[0] = make_uint4(*reinterpret_cast<uint32_t*>(&h0),
                               *reinterpret_cast<uint32_t*>(&h1),
                               *reinterpret_cast<uint32_t*>(&h2),
                               *reinterpret_cast<uint32_t*>(&h3));
            rh[1] = make_uint4(*reinterpret_cast<uint32_t*>(&h4), 0u, 0u, 0u);
        }
        __syncwarp();

        // --- ldmatrix for BOTH rowgroups (frees the smem buffer)
        uint32_t a0[4], a1[4];
        {
            const uint32_t rbase =
                (uint32_t)((lane & 7) + ((lane >> 3) & 1) * 8) * 48 +
                (uint32_t)(lane >> 4) * 16;
            asm volatile("ldmatrix.sync.aligned.m8n8.x4.shared.b16 {%0,%1,%2,%3}, [%4];"
                : "=r"(a0[0]), "=r"(a0[1]), "=r"(a0[2]), "=r"(a0[3])
                : "r"(abase + rbase));
            asm volatile("ldmatrix.sync.aligned.m8n8.x4.shared.b16 {%0,%1,%2,%3}, [%4];"
                : "=r"(a1[0]), "=r"(a1[1]), "=r"(a1[2]), "=r"(a1[3])
                : "r"(abase + 16 * 48 + rbase));
        }
        const int ox_rg0a = s_ox[wid][bg];
        const int ox_rg0b = s_ox[wid][bg + 8];
        const int ox_rg1a = s_ox[wid][16 + bg];
        const int ox_rg1b = s_ox[wid][16 + bg + 8];
        __syncwarp();

        // --- ISSUE next tile's gather now; latency hides under mma/stores
        {
            const int nt = (tile + nwarps < ntiles) ? tile + nwarps : 0;
            const int q0 = nt * 32;
            const float2* rb = g_cell + (q0 >> 11) * GW2 + (q0 & (WW - 1)) + lane;
            const float2 center = rb[GW2 + 1];
            oidx = __float_as_int(center.y);
            s[0] = rb[0].x;       s[1] = rb[1].x;       s[2] = rb[2].x;
            s[3] = rb[GW2].x;     s[4] = center.x;      s[5] = rb[GW2 + 2].x;
            s[6] = rb[2*GW2].x;   s[7] = rb[2*GW2+1].x; s[8] = rb[2*GW2+2].x;
        }

        // --- mma + stores, rowgroup 0
#pragma unroll
        for (int nb = 0; nb < 8; nb++) {
            float c0 = 0.f, c1 = 0.f, c2 = 0.f, c3 = 0.f;
            asm volatile(
                "mma.sync.aligned.m16n8k16.row.col.f32.f16.f16.f32 "
                "{%0,%1,%2,%3}, {%4,%5,%6,%7}, {%8,%9}, {%0,%1,%2,%3};"
                : "+f"(c0), "+f"(c1), "+f"(c2), "+f"(c3)
                : "r"(a0[0]), "r"(a0[1]), "r"(a0[2]), "r"(a0[3]),
                  "r"(bh[nb][0]), "r"(bh[nb][1]));
            asm volatile(
                "mma.sync.aligned.m16n8k16.row.col.f32.f16.f16.f32 "
                "{%0,%1,%2,%3}, {%4,%5,%6,%7}, {%8,%9}, {%0,%1,%2,%3};"
                : "+f"(c0), "+f"(c1), "+f"(c2), "+f"(c3)
                : "r"(a0[0]), "r"(a0[1]), "r"(a0[2]), "r"(a0[3]),
                  "r"(bl[nb][0]), "r"(bl[nb][1]));
            const int colf2 = nb * 4 + btg;
            if (ox_rg0a > 0) {
                float2 v = make_float2(fmaxf(c0, 0.f), fmaxf(c1, 0.f));
                __stcs(&out2[(size_t)(ox_rg0a - 1) * 32 + colf2], v);
            }
            if (ox_rg0b > 0) {
                float2 v = make_float2(fmaxf(c2, 0.f), fmaxf(c3, 0.f));
                __stcs(&out2[(size_t)(ox_rg0b - 1) * 32 + colf2], v);
            }
        }
        // --- mma + stores, rowgroup 1
#pragma unroll
        for (int nb = 0; nb < 8; nb++) {
            float c0 = 0.f, c1 = 0.f, c2 = 0.f, c3 = 0.f;
            asm volatile(
                "mma.sync.aligned.m16n8k16.row.col.f32.f16.f16.f32 "
                "{%0,%1,%2,%3}, {%4,%5,%6,%7}, {%8,%9}, {%0,%1,%2,%3};"
                : "+f"(c0), "+f"(c1), "+f"(c2), "+f"(c3)
                : "r"(a1[0]), "r"(a1[1]), "r"(a1[2]), "r"(a1[3]),
                  "r"(bh[nb][0]), "r"(bh[nb][1]));
            asm volatile(
                "mma.sync.aligned.m16n8k16.row.col.f32.f16.f16.f32 "
                "{%0,%1,%2,%3}, {%4,%5,%6,%7}, {%8,%9}, {%0,%1,%2,%3};"
                : "+f"(c0), "+f"(c1), "+f"(c2), "+f"(c3)
                : "r"(a1[0]), "r"(a1[1]), "r"(a1[2]), "r"(a1[3]),
                  "r"(bl[nb][0]), "r"(bl[nb][1]));
            const int colf2 = nb * 4 + btg;
            if (ox_rg1a > 0) {
                float2 v = make_float2(fmaxf(c0, 0.f), fmaxf(c1, 0.f));
                __stcs(&out2[(size_t)(ox_rg1a - 1) * 32 + colf2], v);
            }
            if (ox_rg1b > 0) {
                float2 v = make_float2(fmaxf(c2, 0.f), fmaxf(c3, 0.f));
                __stcs(&out2[(size_t)(ox_rg1b - 1) * 32 + colf2], v);
            }
        }
        __syncwarp();
    }
}

// ---------------------------------------------------------------------------
// Launch: inputs are feats[N,1] f32, weight[9,1,64] f32, gamma[64], beta[64],
//         coords[N,2] i32. Output: [N,64] f32.
// ---------------------------------------------------------------------------
extern "C" void kernel_launch(void* const* d_in, const int* in_sizes, int n_in,
                              void* d_out, int out_size) {
    const float* feats  = (const float*)d_in[0];
    const float* weight = (const float*)d_in[1];
    const float* gamma  = (const float*)d_in[2];
    const float* beta   = (const float*)d_in[3];
    const int2*  coords = (const int2*)d_in[4];
    const int n = in_sizes[0];   // N (C_IN = 1)

    k_scatter<<<1024, 256>>>(coords, feats, n);
    k_stats<<<STATS_BLOCKS, 256>>>(weight, gamma, beta, n);
    k_output<<<OUT_BLOCKS, 256>>>((float*)d_out);
}